// round 2
// baseline (speedup 1.0000x reference)
#include <cuda_runtime.h>

// Problem constants
#define B_   2
#define T_   2048
#define D_   1024
#define H_   16
#define S_   16
#define HD_  64
#define BT_  (B_ * T_)     // 4096
#define N3D_ (3 * D_)      // 3072

// ---------------------------------------------------------------------------
// Workspaces (device globals — no allocation allowed)
// ---------------------------------------------------------------------------
__device__ float g_qkv[BT_ * N3D_];          // (b,t,{q,k,v},h,hd) = 50.3 MB
__device__ float g_attno[BT_ * D_];          // attention output (b,t,h,hd)
__device__ float g_qwa[B_ * H_ * T_ * S_];   // q splat weights * amplitude
__device__ float g_kw [B_ * H_ * T_ * S_];   // k splat weights
__device__ float g_centers[H_ * S_ * HD_];
__device__ float g_invvar[H_ * S_];
__device__ float g_amp[H_ * S_];
__device__ float g_shift[H_];                // per-head logit shift (softmax stability)
__device__ float g_invtemp;

typedef unsigned long long u64;

// ---------------------------------------------------------------------------
// Packed f32x2 helpers (FFMA2 — full-rate fp32 on Blackwell sm_100+)
// ---------------------------------------------------------------------------
__device__ __forceinline__ u64 pack2(float lo, float hi) {
    u64 r;
    asm("mov.b64 %0, {%1, %2};" : "=l"(r) : "f"(lo), "f"(hi));
    return r;
}
__device__ __forceinline__ u64 fma2(u64 a, u64 b, u64 c) {
    u64 d;
    asm("fma.rn.f32x2 %0, %1, %2, %3;" : "=l"(d) : "l"(a), "l"(b), "l"(c));
    return d;
}
__device__ __forceinline__ void unpack2(u64 v, float& lo, float& hi) {
    asm("mov.b64 {%0, %1}, %2;" : "=f"(lo), "=f"(hi) : "l"(v));
}

// ---------------------------------------------------------------------------
// Kernel 1: splat parameters (tiny)
// ---------------------------------------------------------------------------
__global__ void params_kernel(const float* __restrict__ sc, const float* __restrict__ sd,
                              const float* __restrict__ ls, const float* __restrict__ la,
                              const float* __restrict__ ms, const float* __restrict__ temp) {
    const int tid = threadIdx.x;
    const float sig = 1.0f / (1.0f + expf(-ms[0]));
    const float mv = sig * 0.2f;
    for (int i = tid; i < H_ * S_ * HD_; i += 256)
        g_centers[i] = sc[i] + sd[i] * mv;
    {
        float scale = fminf(fmaxf(expf(ls[tid]), 0.01f), 2.0f);
        g_invvar[tid] = -0.5f / (scale * scale + 1e-8f);
        g_amp[tid] = fminf(fmaxf(expf(la[tid]), 1e-6f), 10.0f);
    }
    __syncthreads();
    if (tid < H_) {
        float t = fminf(fmaxf(temp[0], 0.1f), 10.0f);
        float it = 1.0f / t;
        float ssum = 0.0f;
        for (int s = 0; s < S_; s++) ssum += g_amp[tid * S_ + s];
        g_shift[tid] = 0.5f * ssum * it;   // logits in [0, ssum*it] -> exponent in [-C, C]
        if (tid == 0) g_invtemp = it;
    }
}

// ---------------------------------------------------------------------------
// NT SGEMM body  C[m,n] = sum_k A[m,k] * Bw[n,k]
// 128x128 tile, BK=16, 256 threads, 8x8/thread via f32x2 pairs.
// M,N,K all multiples of tile dims for this problem (no bounds checks).
// ---------------------------------------------------------------------------
__device__ __forceinline__ void sgemm_nt_body(
    const float* __restrict__ A, const float* __restrict__ Bw,
    float* __restrict__ C, int M, int N, int K)
{
    __shared__ float As[16][132];
    __shared__ float Bs[16][132];
    const int tid = threadIdx.x;
    const int tx = tid & 15, ty = tid >> 4;
    const int m0 = blockIdx.y * 128, n0 = blockIdx.x * 128;
    const int lr = tid >> 2;           // 0..63
    const int lc = (tid & 3) << 2;     // 0,4,8,12

    const float* Ap0 = A + (size_t)(m0 + lr) * K + lc;
    const float* Ap1 = A + (size_t)(m0 + lr + 64) * K + lc;
    const float* Bp0 = Bw + (size_t)(n0 + lr) * K + lc;
    const float* Bp1 = Bw + (size_t)(n0 + lr + 64) * K + lc;

    u64 acc[8][4];
#pragma unroll
    for (int i = 0; i < 8; i++)
#pragma unroll
        for (int j = 0; j < 4; j++) acc[i][j] = 0ull;

    // prefetch first tile
    float4 ra0 = *(const float4*)Ap0;
    float4 ra1 = *(const float4*)Ap1;
    float4 rb0 = *(const float4*)Bp0;
    float4 rb1 = *(const float4*)Bp1;

    for (int k0 = 0; k0 < K; k0 += 16) {
        As[lc + 0][lr] = ra0.x; As[lc + 1][lr] = ra0.y; As[lc + 2][lr] = ra0.z; As[lc + 3][lr] = ra0.w;
        As[lc + 0][lr + 64] = ra1.x; As[lc + 1][lr + 64] = ra1.y; As[lc + 2][lr + 64] = ra1.z; As[lc + 3][lr + 64] = ra1.w;
        Bs[lc + 0][lr] = rb0.x; Bs[lc + 1][lr] = rb0.y; Bs[lc + 2][lr] = rb0.z; Bs[lc + 3][lr] = rb0.w;
        Bs[lc + 0][lr + 64] = rb1.x; Bs[lc + 1][lr + 64] = rb1.y; Bs[lc + 2][lr + 64] = rb1.z; Bs[lc + 3][lr + 64] = rb1.w;
        __syncthreads();

        if (k0 + 16 < K) {
            ra0 = *(const float4*)(Ap0 + k0 + 16);
            ra1 = *(const float4*)(Ap1 + k0 + 16);
            rb0 = *(const float4*)(Bp0 + k0 + 16);
            rb1 = *(const float4*)(Bp1 + k0 + 16);
        }

#pragma unroll
        for (int k = 0; k < 16; k++) {
            float av[8];
            *(float4*)&av[0] = *(const float4*)&As[k][ty * 8];
            *(float4*)&av[4] = *(const float4*)&As[k][ty * 8 + 4];
            const u64* bp = (const u64*)&Bs[k][tx * 8];
            u64 b0 = bp[0], b1 = bp[1], b2 = bp[2], b3 = bp[3];
#pragma unroll
            for (int i = 0; i < 8; i++) {
                u64 ap = pack2(av[i], av[i]);
                acc[i][0] = fma2(ap, b0, acc[i][0]);
                acc[i][1] = fma2(ap, b1, acc[i][1]);
                acc[i][2] = fma2(ap, b2, acc[i][2]);
                acc[i][3] = fma2(ap, b3, acc[i][3]);
            }
        }
        __syncthreads();
    }

#pragma unroll
    for (int i = 0; i < 8; i++) {
        float out[8];
#pragma unroll
        for (int j = 0; j < 4; j++) unpack2(acc[i][j], out[2 * j], out[2 * j + 1]);
        float* cp = C + (size_t)(m0 + ty * 8 + i) * N + n0 + tx * 8;
        *(float4*)cp       = make_float4(out[0], out[1], out[2], out[3]);
        *(float4*)(cp + 4) = make_float4(out[4], out[5], out[6], out[7]);
    }
}

// Thin wrappers binding device-global workspaces (no host symbol lookups needed)
__global__ __launch_bounds__(256) void qkv_gemm_kernel(
    const float* __restrict__ x, const float* __restrict__ qkv_w) {
    sgemm_nt_body(x, qkv_w, g_qkv, BT_, N3D_, D_);
}
__global__ __launch_bounds__(256) void out_gemm_kernel(
    const float* __restrict__ out_w, float* __restrict__ out) {
    sgemm_nt_body(g_attno, out_w, out, BT_, D_, D_);
}

// ---------------------------------------------------------------------------
// Kernel 3: splat weights.  block = 16 tokens x 16 splats, grid (T/16, B*H)
// ---------------------------------------------------------------------------
__global__ __launch_bounds__(256) void splat_weights_kernel() {
    __shared__ float qsm[16][65], ksm2[16][65], csm[16][65];
    __shared__ float ivv[16], amps[16];
    const int tid = threadIdx.x;
    const int bh = blockIdx.y, b = bh >> 4, h = bh & 15;
    const int t0 = blockIdx.x * 16;

    for (int idx = tid; idx < 16 * 64; idx += 256) {
        int s = idx >> 6, d = idx & 63;
        csm[s][d] = g_centers[(h * 16 + s) * 64 + d];
    }
    if (tid < 16) { ivv[tid] = g_invvar[h * 16 + tid]; amps[tid] = g_amp[h * 16 + tid]; }
    for (int idx = tid; idx < 16 * 64; idx += 256) {
        int tt = idx >> 6, d = idx & 63;
        size_t base = ((size_t)(b * T_ + t0 + tt) * 3) * D_ + h * 64 + d;
        qsm[tt][d] = g_qkv[base];          // q (w=0)
        ksm2[tt][d] = g_qkv[base + D_];    // k (w=1)
    }
    __syncthreads();

    const int s = tid & 15, tt = tid >> 4;
    float dq = 0.0f, dk = 0.0f;
#pragma unroll
    for (int d = 0; d < 64; d++) {
        float c = csm[s][d];
        float x1 = qsm[tt][d] - c; dq = fmaf(x1, x1, dq);
        float x2 = ksm2[tt][d] - c; dk = fmaf(x2, x2, dk);
    }
    size_t oidx = ((size_t)bh * T_ + t0 + tt) * S_ + s;
    g_qwa[oidx] = __expf(dq * ivv[s]) * amps[s];
    g_kw[oidx]  = __expf(dk * ivv[s]);
}

// ---------------------------------------------------------------------------
// Kernel 4: flash attention over splat weights.
//   logits[i,j] = sum_s qwa[i,s]*kw[j,s];  p = exp(l*invtemp - shift)
//   o[i,d] = sum_j p * v[j,d];  divide by rowsum at the end.
// block: 128 query rows, 256 threads; j-tiles of 32. grid (T/128, B*H)
// ---------------------------------------------------------------------------
__global__ __launch_bounds__(256) void flash_kernel() {
    __shared__ float qs[16][128];      // [s][m]
    __shared__ float ksh[16][36];      // [s][j]
    __shared__ float Es[32][132];      // [j][m]
    __shared__ float Vs[32][68];       // [j][d]
    __shared__ float psum[128][17];    // per-row partial sums, per tx slot
    __shared__ float rsum[128];

    const int tid = threadIdx.x;
    const int bh = blockIdx.y, b = bh >> 4, h = bh & 15;
    const int i0 = blockIdx.x * 128;
    const float* qwa = g_qwa + ((size_t)bh * T_ + i0) * S_;
    const float* kwp = g_kw + (size_t)bh * T_ * S_;
    const float* vp  = g_qkv + ((size_t)b * T_ * 3 + 2) * D_ + h * HD_;  // row stride 3072
    const float invtemp = g_invtemp;
    const float shift = g_shift[h];

    // load qwa tile transposed [s][m]
    for (int f = tid; f < 512; f += 256) {
        int r = f >> 2, c4 = (f & 3) << 2;
        float4 v = *(const float4*)(qwa + r * 16 + c4);
        qs[c4 + 0][r] = v.x; qs[c4 + 1][r] = v.y; qs[c4 + 2][r] = v.z; qs[c4 + 3][r] = v.w;
    }
    for (int f = tid; f < 128 * 17; f += 256) (&psum[0][0])[f] = 0.0f;

    const int tx = tid & 15, ty = tid >> 4;
    u64 o2[4][4];                      // [m-pair][d], rows ty*8+2mi, ty*8+2mi+1
#pragma unroll
    for (int i = 0; i < 4; i++)
#pragma unroll
        for (int j = 0; j < 4; j++) o2[i][j] = 0ull;

    for (int j0 = 0; j0 < T_; j0 += 32) {
        if (tid < 128) {               // kw tile 32x16 transposed
            int r = tid >> 2, c4 = (tid & 3) << 2;
            float4 v = *(const float4*)(kwp + (size_t)(j0 + r) * 16 + c4);
            ksh[c4 + 0][r] = v.x; ksh[c4 + 1][r] = v.y; ksh[c4 + 2][r] = v.z; ksh[c4 + 3][r] = v.w;
        }
#pragma unroll
        for (int u = 0; u < 2; u++) {  // V tile 32x64
            int f = tid + u * 256;
            int r = f >> 4, c4 = (f & 15) << 2;
            *(float4*)&Vs[r][c4] = *(const float4*)(vp + (size_t)(j0 + r) * 3072 + c4);
        }
        __syncthreads();

        // ---- stage 1: logits (j = tx*2 + jj), exp, write E tile + rowsums
        {
            u64 l2[2][4];
#pragma unroll
            for (int jj = 0; jj < 2; jj++)
#pragma unroll
                for (int mi = 0; mi < 4; mi++) l2[jj][mi] = 0ull;

#pragma unroll
            for (int s = 0; s < 16; s++) {
                const u64* ap = (const u64*)&qs[s][ty * 8];
                u64 a0 = ap[0], a1 = ap[1], a2 = ap[2], a3 = ap[3];
                float bk0 = ksh[s][tx * 2], bk1 = ksh[s][tx * 2 + 1];
                u64 b0 = pack2(bk0, bk0), b1 = pack2(bk1, bk1);
                l2[0][0] = fma2(a0, b0, l2[0][0]);
                l2[0][1] = fma2(a1, b0, l2[0][1]);
                l2[0][2] = fma2(a2, b0, l2[0][2]);
                l2[0][3] = fma2(a3, b0, l2[0][3]);
                l2[1][0] = fma2(a0, b1, l2[1][0]);
                l2[1][1] = fma2(a1, b1, l2[1][1]);
                l2[1][2] = fma2(a2, b1, l2[1][2]);
                l2[1][3] = fma2(a3, b1, l2[1][3]);
            }
            float p[2][8], rs[8];
#pragma unroll
            for (int rr = 0; rr < 8; rr++) rs[rr] = 0.0f;
#pragma unroll
            for (int jj = 0; jj < 2; jj++) {
#pragma unroll
                for (int mi = 0; mi < 4; mi++) {
                    float lo, hi;
                    unpack2(l2[jj][mi], lo, hi);
                    float e0 = __expf(fmaf(lo, invtemp, -shift));
                    float e1 = __expf(fmaf(hi, invtemp, -shift));
                    p[jj][2 * mi] = e0; p[jj][2 * mi + 1] = e1;
                    rs[2 * mi] += e0; rs[2 * mi + 1] += e1;
                }
                *(float4*)&Es[tx * 2 + jj][ty * 8]     = make_float4(p[jj][0], p[jj][1], p[jj][2], p[jj][3]);
                *(float4*)&Es[tx * 2 + jj][ty * 8 + 4] = make_float4(p[jj][4], p[jj][5], p[jj][6], p[jj][7]);
            }
#pragma unroll
            for (int rr = 0; rr < 8; rr++) psum[ty * 8 + rr][tx] += rs[rr];
        }
        __syncthreads();

        // ---- stage 2: o += E^T(j,m) * V(j,d), register tiled, f32x2 on m-pairs
#pragma unroll 8
        for (int k = 0; k < 32; k++) {
            const u64* ap = (const u64*)&Es[k][ty * 8];
            u64 a0 = ap[0], a1 = ap[1], a2 = ap[2], a3 = ap[3];
            float4 bv = *(const float4*)&Vs[k][tx * 4];
            u64 b0 = pack2(bv.x, bv.x), b1 = pack2(bv.y, bv.y);
            u64 b2 = pack2(bv.z, bv.z), b3 = pack2(bv.w, bv.w);
            o2[0][0] = fma2(a0, b0, o2[0][0]); o2[0][1] = fma2(a0, b1, o2[0][1]);
            o2[0][2] = fma2(a0, b2, o2[0][2]); o2[0][3] = fma2(a0, b3, o2[0][3]);
            o2[1][0] = fma2(a1, b0, o2[1][0]); o2[1][1] = fma2(a1, b1, o2[1][1]);
            o2[1][2] = fma2(a1, b2, o2[1][2]); o2[1][3] = fma2(a1, b3, o2[1][3]);
            o2[2][0] = fma2(a2, b0, o2[2][0]); o2[2][1] = fma2(a2, b1, o2[2][1]);
            o2[2][2] = fma2(a2, b2, o2[2][2]); o2[2][3] = fma2(a2, b3, o2[2][3]);
            o2[3][0] = fma2(a3, b0, o2[3][0]); o2[3][1] = fma2(a3, b1, o2[3][1]);
            o2[3][2] = fma2(a3, b2, o2[3][2]); o2[3][3] = fma2(a3, b3, o2[3][3]);
        }
        __syncthreads();
    }

    if (tid < 128) {
        float s = 0.0f;
#pragma unroll
        for (int x = 0; x < 16; x++) s += psum[tid][x];
        rsum[tid] = s;
    }
    __syncthreads();

#pragma unroll
    for (int mi = 0; mi < 4; mi++) {
        int m = ty * 8 + 2 * mi;
        float inv0 = 1.0f / rsum[m], inv1 = 1.0f / rsum[m + 1];
        float r0[4], r1[4];
#pragma unroll
        for (int d = 0; d < 4; d++) {
            float lo, hi;
            unpack2(o2[mi][d], lo, hi);
            r0[d] = lo * inv0; r1[d] = hi * inv1;
        }
        float* outp = g_attno + ((size_t)(b * T_) + i0 + m) * D_ + h * HD_ + tx * 4;
        *(float4*)outp        = make_float4(r0[0], r0[1], r0[2], r0[3]);
        *(float4*)(outp + D_) = make_float4(r1[0], r1[1], r1[2], r1[3]);
    }
}

// ---------------------------------------------------------------------------
// Launch — kernel launches ONLY (graph-capture safe, no runtime API calls)
// ---------------------------------------------------------------------------
extern "C" void kernel_launch(void* const* d_in, const int* in_sizes, int n_in,
                              void* d_out, int out_size) {
    const float* x     = (const float*)d_in[0];
    const float* sc    = (const float*)d_in[1];
    const float* sd    = (const float*)d_in[2];
    const float* ls    = (const float*)d_in[3];
    const float* la    = (const float*)d_in[4];
    const float* ms    = (const float*)d_in[5];
    const float* temp  = (const float*)d_in[6];
    const float* qkv_w = (const float*)d_in[7];
    const float* out_w = (const float*)d_in[8];
    float* out = (float*)d_out;

    params_kernel<<<1, 256>>>(sc, sd, ls, la, ms, temp);
    qkv_gemm_kernel<<<dim3(N3D_ / 128, BT_ / 128), 256>>>(x, qkv_w);
    splat_weights_kernel<<<dim3(T_ / 16, B_ * H_), 256>>>();
    flash_kernel<<<dim3(T_ / 128, B_ * H_), 256>>>();
    out_gemm_kernel<<<dim3(D_ / 128, BT_ / 128), 256>>>(out_w, out);
}